// round 9
// baseline (speedup 1.0000x reference)
#include <cuda_runtime.h>
#include <cstdint>

// out[b, l] = x[b, perm[b, l]]   (B=1024, L=16384)
// FOUR CTAs per row (grid = 4*B). Each CTA TMA-loads the FULL row into SMEM
// (quadruplicate read dedups in L2, which has headroom), then gathers/stores
// only its quarter. Finer quanta: 9.2 waves -> ~96% tail utilization, and
// shorter decorrelated CTA lifetimes smooth the DRAM read/write mix.

#define THREADS 512
#define SPLIT 4

__global__ __launch_bounds__(THREADS, 3)
void interleave_quarter_kernel(const float* __restrict__ x,
                               const int* __restrict__ perm,
                               float* __restrict__ out,
                               int L) {
    extern __shared__ __align__(128) unsigned char smem_raw[];
    float* srow = reinterpret_cast<float*>(smem_raw);
    uint64_t* mbar_p = reinterpret_cast<uint64_t*>(smem_raw + (size_t)L * sizeof(float));
    uint32_t mbar = (uint32_t)__cvta_generic_to_shared(mbar_p);
    uint32_t sdst = (uint32_t)__cvta_generic_to_shared(srow);

    long long row = blockIdx.x >> 2;          // SPLIT = 4
    int part = blockIdx.x & 3;
    int H = L >> 2;                           // elements per part (4096)
    long long base = row * (long long)L + (long long)part * H;

    const float* xrow  = x + row * (long long)L;
    const int*   ppart = perm + base;
    float*       opart = out + base;

    int tid = threadIdx.x;
    unsigned bytes = (unsigned)L * 4u;

    if (tid == 0) {
        asm volatile("mbarrier.init.shared.b64 [%0], %1;"
                     :: "r"(mbar), "r"(1) : "memory");
    }
    __syncthreads();

    if (tid == 0) {
        uint64_t policy;
        asm volatile("createpolicy.fractional.L2::evict_last.b64 %0, 1.0;"
                     : "=l"(policy));
        asm volatile("mbarrier.arrive.expect_tx.shared.b64 _, [%0], %1;"
                     :: "r"(mbar), "r"(bytes) : "memory");
        asm volatile("cp.async.bulk.shared::cta.global.mbarrier::complete_tx::bytes"
                     ".L2::cache_hint [%0], [%1], %2, [%3], %4;"
                     :: "r"(sdst), "l"(xrow), "r"(bytes), "r"(mbar), "l"(policy)
                     : "memory");
    }

    // Prefetch this quarter's perm (H/4 = 1024 = 2*THREADS int4) while the
    // TMA streams the row. Streaming hint: read-once.
    const int4* p4 = reinterpret_cast<const int4*>(ppart);
    int4 p0 = __ldcs(p4 + tid);
    int4 p1 = __ldcs(p4 + tid + THREADS);

    // Wait for the row.
    {
        uint32_t done;
        asm volatile(
            "{\n\t.reg .pred P;\n\t"
            "mbarrier.try_wait.parity.acquire.cta.shared::cta.b64 P, [%1], %2;\n\t"
            "selp.b32 %0, 1, 0, P;\n\t}"
            : "=r"(done) : "r"(mbar), "r"(0u) : "memory");
        if (!done) {
            asm volatile(
                "{\n\t.reg .pred P;\n\t"
                "W_%=:\n\t"
                "mbarrier.try_wait.parity.acquire.cta.shared::cta.b64 P, [%0], %1, 0x989680;\n\t"
                "@P bra.uni D_%=;\n\t"
                "bra.uni W_%=;\n\t"
                "D_%=:\n\t}"
                :: "r"(mbar), "r"(0u) : "memory");
        }
    }

    // Gather from SMEM, streaming stores.
    float4* o4 = reinterpret_cast<float4*>(opart);
    float4 o;
    o.x = srow[p0.x]; o.y = srow[p0.y]; o.z = srow[p0.z]; o.w = srow[p0.w];
    __stcs(o4 + tid, o);
    o.x = srow[p1.x]; o.y = srow[p1.y]; o.z = srow[p1.z]; o.w = srow[p1.w];
    __stcs(o4 + tid + THREADS, o);
}

extern "C" void kernel_launch(void* const* d_in, const int* in_sizes, int n_in,
                              void* d_out, int out_size) {
    const float* x   = (const float*)d_in[0];
    const int* perm  = (const int*)d_in[1];
    float* out       = (float*)d_out;

    long long total = (long long)in_sizes[1];
    int B = 1024;
    int L = (int)(total / B);

    size_t smem = (size_t)L * sizeof(float) + 16;
    cudaFuncSetAttribute(interleave_quarter_kernel,
                         cudaFuncAttributeMaxDynamicSharedMemorySize, (int)smem);

    interleave_quarter_kernel<<<SPLIT * B, THREADS, smem>>>(x, perm, out, L);
}